// round 14
// baseline (speedup 1.0000x reference)
#include <cuda_runtime.h>
#include <math.h>
#include <stdint.h>

// ---------------- problem constants ----------------
// B=64, T_IN=1000, C_IN=4, F=320, K=26, POOL=13, T_CONV=975, T_POOL=75
// H=320, 3H=960, FLAT=48000, D1=2000, D2=301
static const int KSPLIT_D1 = 60;   // 48000 -> chunks of 800
#define GRU_BLOCKS 160

// ---------------- device scratch (no allocations allowed) ----------------
__device__ float g_convout[62400 * 320];        // (B*975, 320) conv+relu
__device__ float g_pooled [4800 * 320];         // (B*75, 320)
__device__ float g_mx     [2 * 4800 * 960];     // x-projections fw|bw, row = b*75+t
__device__ float g_rkT    [2 * 960 * 320];      // recurrent kernels TRANSPOSED [dir][col][k]
__device__ float g_hT     [4 * 320 * 64];       // [dir][buf] hidden, TRANSPOSED [k][b]
__device__ float g_y      [64 * 48000];         // concat GRU output
__device__ float g_part1  [60 * 64 * 2000];     // dense1 split-K partials
__device__ float g_a1     [64 * 2000];          // dense1 activation
__device__ unsigned g_bar;                      // grid barrier counter (reset each launch)

// ---------------- fp32 GEMM, 8x8/thread, BK=8, double-buffered + prefetch ----------------
// AMODE: 0 = A[row*lda + k]; 1 = conv im2col view A[(row/975)*4000 + (row%975)*4 + k]
// EPI:   0 raw, 1 bias+relu, 2 bias
// kchunk>0: split-K over blockIdx.z, partial at C + z*M*ldc (EPI forced raw)
// Requires K (or kchunk) % 8 == 0, N-base 8-aligned data.
template<int BM,int BN,int AMODE,int EPI>
__global__ __launch_bounds__(256, 2)
void gemm8(const float* __restrict__ A, const float* __restrict__ Bm,
           const float* __restrict__ bias, float* __restrict__ C,
           int M, int N, int K, int lda, int ldb, int ldc, int kchunk)
{
    constexpr int TX = BN / 8, TY = BM / 8;
    static_assert(TX * TY == 256, "need 256 threads");
    __shared__ float sA[2][8][BM + 4];
    __shared__ float sB[2][8][BN];

    const int tid = threadIdx.x;
    const int tx = tid % TX, ty = tid / TX;
    const int m0 = blockIdx.y * BM;
    const int n0 = blockIdx.x * BN;

    int kb = 0, ke = K;
    float* Cout = C;
    if (kchunk > 0) {
        kb = blockIdx.z * kchunk;
        ke = kb + kchunk;
        Cout = C + (size_t)blockIdx.z * (size_t)M * (size_t)ldc;
    }

    // ---- A loader mapping (row fixed across k-tiles) ----
    int alr, alk;
    if constexpr (BM == 256)      { alr = tid;      alk = 0; }
    else if constexpr (BM == 128) { alr = tid >> 1; alk = (tid & 1) * 4; }
    else                          { alr = tid >> 2; alk = (tid & 3) * 2; }
    const int arow = m0 + alr;
    const bool aval = arow < M;
    size_t abase;
    if (AMODE == 1) abase = aval ? (size_t)(arow / 975) * 4000 + (size_t)(arow % 975) * 4 : 0;
    else            abase = aval ? (size_t)arow * (size_t)lda : 0;

    // ---- B loader mapping ----
    const int blk = tid >> 5;                              // 0..7
    const int blc = (BN == 64) ? (tid & 31) * 2 : (tid & 31) * 4;
    const bool fullN = (n0 + BN <= N);

    float4 apre  = make_float4(0.f, 0.f, 0.f, 0.f);
    float4 apre2 = make_float4(0.f, 0.f, 0.f, 0.f);
    float4 bpre0 = make_float4(0.f, 0.f, 0.f, 0.f);
    float4 bpre1 = make_float4(0.f, 0.f, 0.f, 0.f);

    auto loadAB = [&](int k0) {
        if constexpr (BM == 256) {
            if (aval) {
                apre  = *(const float4*)(A + abase + k0);
                apre2 = *(const float4*)(A + abase + k0 + 4);
            }
        } else if constexpr (BM == 128) {
            if (aval) apre = *(const float4*)(A + abase + k0 + alk);
        } else {
            if (aval) { float2 v = *(const float2*)(A + abase + k0 + alk); apre.x = v.x; apre.y = v.y; }
        }
        const float* bp = Bm + (size_t)(k0 + blk) * (size_t)ldb + n0 + blc;
        if constexpr (BN == 64) {
            if (fullN) { float2 v = *(const float2*)bp; bpre0.x = v.x; bpre0.y = v.y; }
            else {
                bpre0.x = (n0 + blc     < N) ? bp[0] : 0.f;
                bpre0.y = (n0 + blc + 1 < N) ? bp[1] : 0.f;
            }
        } else {
            if (fullN) {
                bpre0 = *(const float4*)bp;
                if constexpr (BN == 256) bpre1 = *(const float4*)(bp + 128);
            } else {
                float t0[4];
#pragma unroll
                for (int j = 0; j < 4; j++) t0[j] = (n0 + blc + j < N) ? bp[j] : 0.f;
                bpre0 = make_float4(t0[0], t0[1], t0[2], t0[3]);
                if constexpr (BN == 256) {
                    float t1[4];
#pragma unroll
                    for (int j = 0; j < 4; j++) t1[j] = (n0 + blc + 128 + j < N) ? bp[128 + j] : 0.f;
                    bpre1 = make_float4(t1[0], t1[1], t1[2], t1[3]);
                }
            }
        }
    };
    auto stage = [&](int buf) {
        if constexpr (BM == 256) {
            sA[buf][0][alr] = apre.x;  sA[buf][1][alr] = apre.y;
            sA[buf][2][alr] = apre.z;  sA[buf][3][alr] = apre.w;
            sA[buf][4][alr] = apre2.x; sA[buf][5][alr] = apre2.y;
            sA[buf][6][alr] = apre2.z; sA[buf][7][alr] = apre2.w;
        } else if constexpr (BM == 128) {
            sA[buf][alk + 0][alr] = apre.x; sA[buf][alk + 1][alr] = apre.y;
            sA[buf][alk + 2][alr] = apre.z; sA[buf][alk + 3][alr] = apre.w;
        } else {
            sA[buf][alk + 0][alr] = apre.x; sA[buf][alk + 1][alr] = apre.y;
        }
        if constexpr (BN == 64) {
            sB[buf][blk][blc] = bpre0.x; sB[buf][blk][blc + 1] = bpre0.y;
        } else {
            *(float4*)&sB[buf][blk][blc] = bpre0;
            if constexpr (BN == 256) *(float4*)&sB[buf][blk][blc + 128] = bpre1;
        }
    };

    float acc[8][8];
#pragma unroll
    for (int i = 0; i < 8; i++)
#pragma unroll
        for (int j = 0; j < 8; j++) acc[i][j] = 0.f;

    const int nt = (ke - kb) / 8;
    loadAB(kb);
    stage(0);
    __syncthreads();

    for (int t = 0; t < nt; t++) {
        const int cur = t & 1;
        if (t + 1 < nt) loadAB(kb + (t + 1) * 8);     // LDG in flight during compute
#pragma unroll
        for (int kk = 0; kk < 8; kk++) {
            float4 a0 = *(const float4*)&sA[cur][kk][ty * 8];
            float4 a1 = *(const float4*)&sA[cur][kk][ty * 8 + 4];
            float4 b0 = *(const float4*)&sB[cur][kk][tx * 8];
            float4 b1 = *(const float4*)&sB[cur][kk][tx * 8 + 4];
            float ra[8] = {a0.x, a0.y, a0.z, a0.w, a1.x, a1.y, a1.z, a1.w};
            float rb[8] = {b0.x, b0.y, b0.z, b0.w, b1.x, b1.y, b1.z, b1.w};
#pragma unroll
            for (int i = 0; i < 8; i++)
#pragma unroll
                for (int j = 0; j < 8; j++)
                    acc[i][j] = fmaf(ra[i], rb[j], acc[i][j]);
        }
        if (t + 1 < nt) stage(cur ^ 1);
        __syncthreads();
    }

#pragma unroll
    for (int i = 0; i < 8; i++) {
        int row = m0 + ty * 8 + i;
        if (row >= M) continue;
        float* crow = Cout + (size_t)row * (size_t)ldc;
#pragma unroll
        for (int j = 0; j < 8; j++) {
            int col = n0 + tx * 8 + j;
            if (col >= N) continue;
            float v = acc[i][j];
            if (kchunk == 0) {
                if (EPI == 1)      v = fmaxf(v + bias[col], 0.f);
                else if (EPI == 2) v = v + bias[col];
            }
            crow[col] = v;
        }
    }
}

// ---------------- maxpool over 13 conv rows ----------------
__global__ __launch_bounds__(256)
void pool_kernel(const float* __restrict__ conv, float* __restrict__ pooled)
{
    int idx = blockIdx.x * 256 + threadIdx.x;
    if (idx >= 4800 * 320) return;
    int f = idx % 320;
    int bp = idx / 320;
    int b = bp / 75, p = bp % 75;
    const float* src = conv + ((size_t)(b * 975 + p * 13)) * 320 + f;
    float m = src[0];
#pragma unroll
    for (int q = 1; q < 13; q++) m = fmaxf(m, src[(size_t)q * 320]);
    pooled[idx] = m;
}

// ---------------- transpose rk (320,960) -> rkT (960,320) ----------------
__global__ void transpose_rk(const float* __restrict__ rk, float* __restrict__ rkT)
{
    __shared__ float tile[32][33];
    int c0 = blockIdx.x * 32, k0 = blockIdx.y * 32;
    tile[threadIdx.y][threadIdx.x] = rk[(size_t)(k0 + threadIdx.y) * 960 + c0 + threadIdx.x];
    __syncthreads();
    rkT[(size_t)(c0 + threadIdx.y) * 320 + k0 + threadIdx.x] = tile[threadIdx.x][threadIdx.y];
}

// ---------------- persistent GRU: all 75 steps in ONE kernel ----------------
// grid 160: dir = bid&1, 80 unit-blocks of 4 units per dir.
// threads 256 = {bq:32 batch-pairs} x {ks:8 k-splits}. Each h element is read
// exactly ONCE per block (no duplication). rkT slice (12 rows x 320 k = 15KB)
// staged in smem once for all 75 steps; rk LDS are warp-broadcast (free).
// h reads use __ldcg (L2-coherent; L1 is stale across SMs within one launch).
__global__ __launch_bounds__(256, 2)
void gru_persistent(const float* __restrict__ rkT_all,
                    const float* __restrict__ b_fw,  const float* __restrict__ b_bw,
                    const float* __restrict__ mx_all,
                    float* __restrict__ hT, float* __restrict__ y)
{
    const int bid = blockIdx.x;
    const int dir = bid & 1;
    const int u0  = (bid >> 1) * 4;
    const int tid = threadIdx.x;
    const int bq  = tid & 31;       // batch pair: b = bq*2, bq*2+1
    const int ks  = tid >> 5;       // 0..7, covers k in [ks*40, ks*40+40)

    const float* rkT = rkT_all + (size_t)dir * (960 * 320);
    const float* br  = (dir ? b_bw : b_fw) + 960;
    const float* mxd = mx_all + (size_t)dir * (4800 * 960);
    float* hbase = hT + (size_t)(dir * 2) * 20480;

    __shared__ float srk[12][320];          // c = g*4+uu -> global col g*320+u0+uu
    __shared__ float sred[8 * 64 * 13];     // [ks][b][c] padded to 13

    for (int i = tid; i < 12 * 320; i += 256) {
        int c = i / 320, k = i - c * 320;
        int gcol = (c >> 2) * 320 + u0 + (c & 3);
        srk[c][k] = rkT[(size_t)gcol * 320 + k];
    }
    __syncthreads();

    for (int s = 0; s < 75; s++) {
        const int cur = s & 1;
        const int t   = dir ? (74 - s) : s;
        const float* hcur = hbase + cur * 20480;

        float acc[2][12];
#pragma unroll
        for (int c = 0; c < 12; c++) { acc[0][c] = 0.f; acc[1][c] = 0.f; }

        const int kb = ks * 40;
#pragma unroll 2
        for (int kc = 0; kc < 40; kc += 4) {
            const int k0 = kb + kc;
            float2 hv0 = __ldcg((const float2*)(hcur + (size_t)(k0 + 0) * 64 + bq * 2));
            float2 hv1 = __ldcg((const float2*)(hcur + (size_t)(k0 + 1) * 64 + bq * 2));
            float2 hv2 = __ldcg((const float2*)(hcur + (size_t)(k0 + 2) * 64 + bq * 2));
            float2 hv3 = __ldcg((const float2*)(hcur + (size_t)(k0 + 3) * 64 + bq * 2));
#pragma unroll
            for (int c = 0; c < 12; c++) {
                float4 r = *(const float4*)&srk[c][k0];   // broadcast across bq lanes
                acc[0][c] = fmaf(hv0.x, r.x, acc[0][c]);
                acc[1][c] = fmaf(hv0.y, r.x, acc[1][c]);
                acc[0][c] = fmaf(hv1.x, r.y, acc[0][c]);
                acc[1][c] = fmaf(hv1.y, r.y, acc[1][c]);
                acc[0][c] = fmaf(hv2.x, r.z, acc[0][c]);
                acc[1][c] = fmaf(hv2.y, r.z, acc[1][c]);
                acc[0][c] = fmaf(hv3.x, r.w, acc[0][c]);
                acc[1][c] = fmaf(hv3.y, r.w, acc[1][c]);
            }
        }

        // write k-split partials
#pragma unroll
        for (int i = 0; i < 2; i++) {
            float* p = &sred[((size_t)ks * 64 + bq * 2 + i) * 13];
#pragma unroll
            for (int c = 0; c < 12; c++) p[c] = acc[i][c];
        }
        __syncthreads();

        // gates: one thread per (b, uu)
        {
            const int b  = tid >> 2;
            const int uu = tid & 3;
            const int c  = u0 + uu;
            float sz = 0.f, sr = 0.f, sh = 0.f;
#pragma unroll
            for (int z = 0; z < 8; z++) {
                const float* p = &sred[((size_t)z * 64 + b) * 13];
                sz += p[uu]; sr += p[4 + uu]; sh += p[8 + uu];
            }
            const float* mx = mxd + (size_t)(b * 75 + t) * 960;
            float hold = __ldcg(hcur + (size_t)c * 64 + b);
            float zg   = 1.f / (1.f + expf(-(mx[c]       + sz + br[c])));
            float rg   = 1.f / (1.f + expf(-(mx[320 + c] + sr + br[320 + c])));
            float cand = tanhf(mx[640 + c] + rg * (sh + br[640 + c]));
            float hn   = zg * hold + (1.f - zg) * cand;
            hbase[(size_t)(cur ^ 1) * 20480 + (size_t)c * 64 + b] = hn;
            y[(size_t)b * 48000 + (size_t)t * 640 + dir * 320 + c] = hn;
        }

        // grid barrier (monotonic counter; g_bar reset by memset each launch)
        if (s < 74) {
            __threadfence();
            __syncthreads();          // also protects sred reuse
            if (tid == 0) {
                atomicAdd(&g_bar, 1u);
                const unsigned target = (unsigned)GRU_BLOCKS * (unsigned)(s + 1);
                volatile unsigned* p = &g_bar;
                while (*p < target) __nanosleep(64);
            }
            __syncthreads();
        }
    }
}

// ---------------- dense1 split-K reduce + bias + relu ----------------
__global__ __launch_bounds__(256)
void reduce_relu(const float* __restrict__ part, const float* __restrict__ bias,
                 float* __restrict__ out)
{
    int i = blockIdx.x * 256 + threadIdx.x;
    if (i >= 64 * 2000) return;
    float s = bias[i % 2000];
#pragma unroll 10
    for (int z = 0; z < KSPLIT_D1; z++) s += part[(size_t)z * 128000 + i];
    out[i] = fmaxf(s, 0.f);
}

// ---------------- dense2 + sigmoid ----------------
__global__ void dense2_kernel(const float* __restrict__ a1, const float* __restrict__ w2,
                              const float* __restrict__ b2, float* __restrict__ out)
{
    int n = blockIdx.x * 32 + threadIdx.x;
    int b = blockIdx.y * 8 + threadIdx.y;
    if (n >= 301) return;
    float acc = b2[n];
    const float* arow = a1 + (size_t)b * 2000;
#pragma unroll 4
    for (int k = 0; k < 2000; k++)
        acc = fmaf(arow[k], w2[(size_t)k * 301 + n], acc);
    out[(size_t)b * 301 + n] = 1.f / (1.f + expf(-acc));
}

// ---------------- launcher ----------------
extern "C" void kernel_launch(void* const* d_in, const int* in_sizes, int n_in,
                              void* d_out, int out_size)
{
    const float* inputs = (const float*)d_in[0];
    const float* conv_w = (const float*)d_in[1];
    const float* conv_b = (const float*)d_in[2];
    const float* fw_k   = (const float*)d_in[3];
    const float* fw_rk  = (const float*)d_in[4];
    const float* fw_b   = (const float*)d_in[5];
    const float* bw_k   = (const float*)d_in[6];
    const float* bw_rk  = (const float*)d_in[7];
    const float* bw_b   = (const float*)d_in[8];
    const float* w1     = (const float*)d_in[9];
    const float* b1     = (const float*)d_in[10];
    const float* w2     = (const float*)d_in[11];
    const float* b2     = (const float*)d_in[12];
    float* out = (float*)d_out;

    float *convout, *pooled, *mx, *rkT, *hT, *ybuf, *part1, *a1;
    unsigned* bar;
    cudaGetSymbolAddress((void**)&convout, g_convout);
    cudaGetSymbolAddress((void**)&pooled,  g_pooled);
    cudaGetSymbolAddress((void**)&mx,      g_mx);
    cudaGetSymbolAddress((void**)&rkT,     g_rkT);
    cudaGetSymbolAddress((void**)&hT,      g_hT);
    cudaGetSymbolAddress((void**)&ybuf,    g_y);
    cudaGetSymbolAddress((void**)&part1,   g_part1);
    cudaGetSymbolAddress((void**)&a1,      g_a1);
    cudaGetSymbolAddress((void**)&bar,     g_bar);

    // 0) transpose recurrent kernels for the GRU (done every launch; cheap)
    transpose_rk<<<dim3(30, 10), dim3(32, 32)>>>(fw_rk, rkT);
    transpose_rk<<<dim3(30, 10), dim3(32, 32)>>>(bw_rk, rkT + 960 * 320);

    // 1) Conv1D + bias + relu as GEMM on the stride-4 im2col view (K=104)
    //    BN=64: N=320 exact (no wasted columns)
    gemm8<256,64,1,1><<<dim3(5, 244, 1), 256>>>(
        inputs, conv_w, conv_b, convout, 62400, 320, 104, 4, 320, 320, 0);

    // 2) MaxPool(13)
    pool_kernel<<<(4800 * 320 + 255) / 256, 256>>>(convout, pooled);

    // 3) GRU input projections (+ input bias): 285 blocks = one full wave each
    gemm8<256,64,0,2><<<dim3(15, 19, 1), 256>>>(
        pooled, fw_k, fw_b, mx,               4800, 960, 320, 320, 960, 960, 0);
    gemm8<256,64,0,2><<<dim3(15, 19, 1), 256>>>(
        pooled, bw_k, bw_b, mx + 4800 * 960,  4800, 960, 320, 320, 960, 960, 0);

    // 4) zero transposed hidden state + grid-barrier counter
    cudaMemsetAsync(hT, 0, 4 * 320 * 64 * sizeof(float));
    cudaMemsetAsync(bar, 0, sizeof(unsigned));

    // 5) all 75 recurrent steps in one persistent kernel
    //    160 blocks x 256 thr, 42KB static smem, <=128 regs -> 2 blocks/SM co-resident
    gru_persistent<<<GRU_BLOCKS, 256>>>(rkT, fw_b, bw_b, mx, hT, ybuf);

    // 6) Dense1 (64,48000)@(48000,2000): 60-way split-K (480 blocks, 2 even waves)
    gemm8<64,256,0,0><<<dim3(8, 1, KSPLIT_D1), 256>>>(
        ybuf, w1, (const float*)0, part1, 64, 2000, 48000, 48000, 2000, 2000, 800);
    reduce_relu<<<(64 * 2000 + 255) / 256, 256>>>(part1, b1, a1);

    // 7) Dense2 + sigmoid
    dense2_kernel<<<dim3(10, 8), dim3(32, 8)>>>(a1, w2, b2, out);

    (void)in_sizes; (void)n_in; (void)out_size;
}

// round 15
// speedup vs baseline: 1.0329x; 1.0329x over previous
#include <cuda_runtime.h>
#include <math.h>
#include <stdint.h>

// ---------------- problem constants ----------------
// B=64, T_IN=1000, C_IN=4, F=320, K=26, POOL=13, T_CONV=975, T_POOL=75
// H=320, 3H=960, FLAT=48000, D1=2000, D2=301
static const int KSPLIT_D1 = 60;   // 48000 -> chunks of 800
#define GRU_BLOCKS 160

// ---------------- device scratch (no allocations allowed) ----------------
__device__ float g_convout[62400 * 320];        // (B*975, 320) conv+relu
__device__ float g_pooled [4800 * 320];         // (B*75, 320)
__device__ float g_mx     [2 * 4800 * 960];     // x-projections fw|bw, row = b*75+t
__device__ float g_rkT    [2 * 960 * 320];      // recurrent kernels TRANSPOSED [dir][col][k]
__device__ float g_hT     [4 * 320 * 64];       // [dir][buf] hidden, TRANSPOSED [k][b]
__device__ float g_y      [64 * 48000];         // concat GRU output
__device__ float g_part1  [60 * 64 * 2000];     // dense1 split-K partials
__device__ float g_a1     [64 * 2000];          // dense1 activation
__device__ unsigned g_bar;                      // grid barrier counter (reset each launch)

// ---------------- packed fp32x2 FMA (B300: 2x fp32 throughput, full precision) ----
__device__ __forceinline__ void ffma2(unsigned long long& d,
                                      unsigned long long a,
                                      unsigned long long b) {
    asm("fma.rn.f32x2 %0, %1, %2, %0;" : "+l"(d) : "l"(a), "l"(b));
}
__device__ __forceinline__ unsigned long long pack2(float x) {
    unsigned long long r;
    asm("mov.b64 %0, {%1, %1};" : "=l"(r) : "f"(x));
    return r;
}
__device__ __forceinline__ void unpack2(unsigned long long v, float& lo, float& hi) {
    asm("mov.b64 {%0, %1}, %2;" : "=f"(lo), "=f"(hi) : "l"(v));
}

// ---------------- fp32 GEMM, 8x8/thread via FFMA2, BK=8, double-buffered ----------------
// AMODE: 0 = A[row*lda + k]; 1 = conv im2col view A[(row/975)*4000 + (row%975)*4 + k]
// EPI:   0 raw, 1 bias+relu, 2 bias
// kchunk>0: split-K over blockIdx.z, partial at C + z*M*ldc (EPI forced raw)
// Requires K (or kchunk) % 8 == 0.
template<int BM,int BN,int AMODE,int EPI>
__global__ __launch_bounds__(256, 2)
void gemm8(const float* __restrict__ A, const float* __restrict__ Bm,
           const float* __restrict__ bias, float* __restrict__ C,
           int M, int N, int K, int lda, int ldb, int ldc, int kchunk)
{
    constexpr int TX = BN / 8, TY = BM / 8;
    static_assert(TX * TY == 256, "need 256 threads");
    __shared__ float sA[2][8][BM + 4];
    __shared__ __align__(16) float sB[2][8][BN];

    const int tid = threadIdx.x;
    const int tx = tid % TX, ty = tid / TX;
    const int m0 = blockIdx.y * BM;
    const int n0 = blockIdx.x * BN;

    int kb = 0, ke = K;
    float* Cout = C;
    if (kchunk > 0) {
        kb = blockIdx.z * kchunk;
        ke = kb + kchunk;
        Cout = C + (size_t)blockIdx.z * (size_t)M * (size_t)ldc;
    }

    // ---- A loader mapping (row fixed across k-tiles) ----
    int alr, alk;
    if constexpr (BM == 256)      { alr = tid;      alk = 0; }
    else if constexpr (BM == 128) { alr = tid >> 1; alk = (tid & 1) * 4; }
    else                          { alr = tid >> 2; alk = (tid & 3) * 2; }
    const int arow = m0 + alr;
    const bool aval = arow < M;
    size_t abase;
    if (AMODE == 1) abase = aval ? (size_t)(arow / 975) * 4000 + (size_t)(arow % 975) * 4 : 0;
    else            abase = aval ? (size_t)arow * (size_t)lda : 0;

    // ---- B loader mapping ----
    const int blk = tid >> 5;                              // 0..7
    const int blc = (BN == 64) ? (tid & 31) * 2 : (tid & 31) * 4;
    const bool fullN = (n0 + BN <= N);

    float4 apre  = make_float4(0.f, 0.f, 0.f, 0.f);
    float4 apre2 = make_float4(0.f, 0.f, 0.f, 0.f);
    float4 bpre0 = make_float4(0.f, 0.f, 0.f, 0.f);
    float4 bpre1 = make_float4(0.f, 0.f, 0.f, 0.f);

    auto loadAB = [&](int k0) {
        if constexpr (BM == 256) {
            if (aval) {
                apre  = *(const float4*)(A + abase + k0);
                apre2 = *(const float4*)(A + abase + k0 + 4);
            }
        } else if constexpr (BM == 128) {
            if (aval) apre = *(const float4*)(A + abase + k0 + alk);
        } else {
            if (aval) { float2 v = *(const float2*)(A + abase + k0 + alk); apre.x = v.x; apre.y = v.y; }
        }
        const float* bp = Bm + (size_t)(k0 + blk) * (size_t)ldb + n0 + blc;
        if constexpr (BN == 64) {
            if (fullN) { float2 v = *(const float2*)bp; bpre0.x = v.x; bpre0.y = v.y; }
            else {
                bpre0.x = (n0 + blc     < N) ? bp[0] : 0.f;
                bpre0.y = (n0 + blc + 1 < N) ? bp[1] : 0.f;
            }
        } else {
            if (fullN) {
                bpre0 = *(const float4*)bp;
                if constexpr (BN == 256) bpre1 = *(const float4*)(bp + 128);
            } else {
                float t0[4];
#pragma unroll
                for (int j = 0; j < 4; j++) t0[j] = (n0 + blc + j < N) ? bp[j] : 0.f;
                bpre0 = make_float4(t0[0], t0[1], t0[2], t0[3]);
                if constexpr (BN == 256) {
                    float t1[4];
#pragma unroll
                    for (int j = 0; j < 4; j++) t1[j] = (n0 + blc + 128 + j < N) ? bp[128 + j] : 0.f;
                    bpre1 = make_float4(t1[0], t1[1], t1[2], t1[3]);
                }
            }
        }
    };
    auto stage = [&](int buf) {
        if constexpr (BM == 256) {
            sA[buf][0][alr] = apre.x;  sA[buf][1][alr] = apre.y;
            sA[buf][2][alr] = apre.z;  sA[buf][3][alr] = apre.w;
            sA[buf][4][alr] = apre2.x; sA[buf][5][alr] = apre2.y;
            sA[buf][6][alr] = apre2.z; sA[buf][7][alr] = apre2.w;
        } else if constexpr (BM == 128) {
            sA[buf][alk + 0][alr] = apre.x; sA[buf][alk + 1][alr] = apre.y;
            sA[buf][alk + 2][alr] = apre.z; sA[buf][alk + 3][alr] = apre.w;
        } else {
            sA[buf][alk + 0][alr] = apre.x; sA[buf][alk + 1][alr] = apre.y;
        }
        if constexpr (BN == 64) {
            sB[buf][blk][blc] = bpre0.x; sB[buf][blk][blc + 1] = bpre0.y;
        } else {
            *(float4*)&sB[buf][blk][blc] = bpre0;
            if constexpr (BN == 256) *(float4*)&sB[buf][blk][blc + 128] = bpre1;
        }
    };

    // packed accumulators: acc2[i][j] holds cols (tx*8+2j, tx*8+2j+1) for row ty*8+i
    unsigned long long acc2[8][4];
#pragma unroll
    for (int i = 0; i < 8; i++)
#pragma unroll
        for (int j = 0; j < 4; j++) acc2[i][j] = 0ull;

    const int nt = (ke - kb) / 8;
    loadAB(kb);
    stage(0);
    __syncthreads();

    for (int t = 0; t < nt; t++) {
        const int cur = t & 1;
        if (t + 1 < nt) loadAB(kb + (t + 1) * 8);     // LDG in flight during compute
#pragma unroll
        for (int kk = 0; kk < 8; kk++) {
            float4 a0 = *(const float4*)&sA[cur][kk][ty * 8];
            float4 a1 = *(const float4*)&sA[cur][kk][ty * 8 + 4];
            const unsigned long long* bp =
                (const unsigned long long*)&sB[cur][kk][tx * 8];   // 8-byte aligned
            unsigned long long b2[4] = {bp[0], bp[1], bp[2], bp[3]};
            float ra[8] = {a0.x, a0.y, a0.z, a0.w, a1.x, a1.y, a1.z, a1.w};
#pragma unroll
            for (int i = 0; i < 8; i++) {
                unsigned long long ap = pack2(ra[i]);
                ffma2(acc2[i][0], ap, b2[0]);
                ffma2(acc2[i][1], ap, b2[1]);
                ffma2(acc2[i][2], ap, b2[2]);
                ffma2(acc2[i][3], ap, b2[3]);
            }
        }
        if (t + 1 < nt) stage(cur ^ 1);
        __syncthreads();
    }

#pragma unroll
    for (int i = 0; i < 8; i++) {
        int row = m0 + ty * 8 + i;
        if (row >= M) continue;
        float* crow = Cout + (size_t)row * (size_t)ldc;
#pragma unroll
        for (int j = 0; j < 4; j++) {
            float lo, hi;
            unpack2(acc2[i][j], lo, hi);
#pragma unroll
            for (int e = 0; e < 2; e++) {
                int col = n0 + tx * 8 + 2 * j + e;
                if (col >= N) continue;
                float v = e ? hi : lo;
                if (kchunk == 0) {
                    if (EPI == 1)      v = fmaxf(v + bias[col], 0.f);
                    else if (EPI == 2) v = v + bias[col];
                }
                crow[col] = v;
            }
        }
    }
}

// ---------------- maxpool over 13 conv rows ----------------
__global__ __launch_bounds__(256)
void pool_kernel(const float* __restrict__ conv, float* __restrict__ pooled)
{
    int idx = blockIdx.x * 256 + threadIdx.x;
    if (idx >= 4800 * 320) return;
    int f = idx % 320;
    int bp = idx / 320;
    int b = bp / 75, p = bp % 75;
    const float* src = conv + ((size_t)(b * 975 + p * 13)) * 320 + f;
    float m = src[0];
#pragma unroll
    for (int q = 1; q < 13; q++) m = fmaxf(m, src[(size_t)q * 320]);
    pooled[idx] = m;
}

// ---------------- transpose rk (320,960) -> rkT (960,320) ----------------
__global__ void transpose_rk(const float* __restrict__ rk, float* __restrict__ rkT)
{
    __shared__ float tile[32][33];
    int c0 = blockIdx.x * 32, k0 = blockIdx.y * 32;
    tile[threadIdx.y][threadIdx.x] = rk[(size_t)(k0 + threadIdx.y) * 960 + c0 + threadIdx.x];
    __syncthreads();
    rkT[(size_t)(c0 + threadIdx.y) * 320 + k0 + threadIdx.x] = tile[threadIdx.x][threadIdx.y];
}

// ---------------- persistent GRU: all 75 steps in ONE kernel ----------------
// grid 160: dir = bid&1, 80 unit-blocks of 4 units per dir.
// threads 256 = {bq:32 batch-pairs} x {ks:8 k-splits}. Each h element is read
// exactly ONCE per block. rkT slice staged in smem once for all 75 steps.
// h reads use __ldcg (L2-coherent; L1 is stale across SMs within one launch).
__global__ __launch_bounds__(256, 2)
void gru_persistent(const float* __restrict__ rkT_all,
                    const float* __restrict__ b_fw,  const float* __restrict__ b_bw,
                    const float* __restrict__ mx_all,
                    float* __restrict__ hT, float* __restrict__ y)
{
    const int bid = blockIdx.x;
    const int dir = bid & 1;
    const int u0  = (bid >> 1) * 4;
    const int tid = threadIdx.x;
    const int bq  = tid & 31;       // batch pair: b = bq*2, bq*2+1
    const int ks  = tid >> 5;       // 0..7, covers k in [ks*40, ks*40+40)

    const float* rkT = rkT_all + (size_t)dir * (960 * 320);
    const float* br  = (dir ? b_bw : b_fw) + 960;
    const float* mxd = mx_all + (size_t)dir * (4800 * 960);
    float* hbase = hT + (size_t)(dir * 2) * 20480;

    __shared__ float srk[12][320];          // c = g*4+uu -> global col g*320+u0+uu
    __shared__ float sred[8 * 64 * 13];     // [ks][b][c] padded to 13

    for (int i = tid; i < 12 * 320; i += 256) {
        int c = i / 320, k = i - c * 320;
        int gcol = (c >> 2) * 320 + u0 + (c & 3);
        srk[c][k] = rkT[(size_t)gcol * 320 + k];
    }
    __syncthreads();

    for (int s = 0; s < 75; s++) {
        const int cur = s & 1;
        const int t   = dir ? (74 - s) : s;
        const float* hcur = hbase + cur * 20480;

        float acc[2][12];
#pragma unroll
        for (int c = 0; c < 12; c++) { acc[0][c] = 0.f; acc[1][c] = 0.f; }

        const int kb = ks * 40;
#pragma unroll 2
        for (int kc = 0; kc < 40; kc += 4) {
            const int k0 = kb + kc;
            float2 hv0 = __ldcg((const float2*)(hcur + (size_t)(k0 + 0) * 64 + bq * 2));
            float2 hv1 = __ldcg((const float2*)(hcur + (size_t)(k0 + 1) * 64 + bq * 2));
            float2 hv2 = __ldcg((const float2*)(hcur + (size_t)(k0 + 2) * 64 + bq * 2));
            float2 hv3 = __ldcg((const float2*)(hcur + (size_t)(k0 + 3) * 64 + bq * 2));
#pragma unroll
            for (int c = 0; c < 12; c++) {
                float4 r = *(const float4*)&srk[c][k0];   // broadcast across bq lanes
                acc[0][c] = fmaf(hv0.x, r.x, acc[0][c]);
                acc[1][c] = fmaf(hv0.y, r.x, acc[1][c]);
                acc[0][c] = fmaf(hv1.x, r.y, acc[0][c]);
                acc[1][c] = fmaf(hv1.y, r.y, acc[1][c]);
                acc[0][c] = fmaf(hv2.x, r.z, acc[0][c]);
                acc[1][c] = fmaf(hv2.y, r.z, acc[1][c]);
                acc[0][c] = fmaf(hv3.x, r.w, acc[0][c]);
                acc[1][c] = fmaf(hv3.y, r.w, acc[1][c]);
            }
        }

        // write k-split partials
#pragma unroll
        for (int i = 0; i < 2; i++) {
            float* p = &sred[((size_t)ks * 64 + bq * 2 + i) * 13];
#pragma unroll
            for (int c = 0; c < 12; c++) p[c] = acc[i][c];
        }
        __syncthreads();

        // gates: one thread per (b, uu)
        {
            const int b  = tid >> 2;
            const int uu = tid & 3;
            const int c  = u0 + uu;
            float sz = 0.f, sr = 0.f, sh = 0.f;
#pragma unroll
            for (int z = 0; z < 8; z++) {
                const float* p = &sred[((size_t)z * 64 + b) * 13];
                sz += p[uu]; sr += p[4 + uu]; sh += p[8 + uu];
            }
            const float* mx = mxd + (size_t)(b * 75 + t) * 960;
            float hold = __ldcg(hcur + (size_t)c * 64 + b);
            float zg   = 1.f / (1.f + expf(-(mx[c]       + sz + br[c])));
            float rg   = 1.f / (1.f + expf(-(mx[320 + c] + sr + br[320 + c])));
            float cand = tanhf(mx[640 + c] + rg * (sh + br[640 + c]));
            float hn   = zg * hold + (1.f - zg) * cand;
            hbase[(size_t)(cur ^ 1) * 20480 + (size_t)c * 64 + b] = hn;
            y[(size_t)b * 48000 + (size_t)t * 640 + dir * 320 + c] = hn;
        }

        // grid barrier (monotonic counter; g_bar reset by memset each launch)
        if (s < 74) {
            __threadfence();
            __syncthreads();          // also protects sred reuse
            if (tid == 0) {
                atomicAdd(&g_bar, 1u);
                const unsigned target = (unsigned)GRU_BLOCKS * (unsigned)(s + 1);
                volatile unsigned* p = &g_bar;
                while (*p < target) __nanosleep(64);
            }
            __syncthreads();
        }
    }
}

// ---------------- dense1 split-K reduce + bias + relu ----------------
__global__ __launch_bounds__(256)
void reduce_relu(const float* __restrict__ part, const float* __restrict__ bias,
                 float* __restrict__ out)
{
    int i = blockIdx.x * 256 + threadIdx.x;
    if (i >= 64 * 2000) return;
    float s = bias[i % 2000];
#pragma unroll 10
    for (int z = 0; z < KSPLIT_D1; z++) s += part[(size_t)z * 128000 + i];
    out[i] = fmaxf(s, 0.f);
}

// ---------------- dense2 + sigmoid ----------------
__global__ void dense2_kernel(const float* __restrict__ a1, const float* __restrict__ w2,
                              const float* __restrict__ b2, float* __restrict__ out)
{
    int n = blockIdx.x * 32 + threadIdx.x;
    int b = blockIdx.y * 8 + threadIdx.y;
    if (n >= 301) return;
    float acc = b2[n];
    const float* arow = a1 + (size_t)b * 2000;
#pragma unroll 4
    for (int k = 0; k < 2000; k++)
        acc = fmaf(arow[k], w2[(size_t)k * 301 + n], acc);
    out[(size_t)b * 301 + n] = 1.f / (1.f + expf(-acc));
}

// ---------------- launcher ----------------
extern "C" void kernel_launch(void* const* d_in, const int* in_sizes, int n_in,
                              void* d_out, int out_size)
{
    const float* inputs = (const float*)d_in[0];
    const float* conv_w = (const float*)d_in[1];
    const float* conv_b = (const float*)d_in[2];
    const float* fw_k   = (const float*)d_in[3];
    const float* fw_rk  = (const float*)d_in[4];
    const float* fw_b   = (const float*)d_in[5];
    const float* bw_k   = (const float*)d_in[6];
    const float* bw_rk  = (const float*)d_in[7];
    const float* bw_b   = (const float*)d_in[8];
    const float* w1     = (const float*)d_in[9];
    const float* b1     = (const float*)d_in[10];
    const float* w2     = (const float*)d_in[11];
    const float* b2     = (const float*)d_in[12];
    float* out = (float*)d_out;

    float *convout, *pooled, *mx, *rkT, *hT, *ybuf, *part1, *a1;
    unsigned* bar;
    cudaGetSymbolAddress((void**)&convout, g_convout);
    cudaGetSymbolAddress((void**)&pooled,  g_pooled);
    cudaGetSymbolAddress((void**)&mx,      g_mx);
    cudaGetSymbolAddress((void**)&rkT,     g_rkT);
    cudaGetSymbolAddress((void**)&hT,      g_hT);
    cudaGetSymbolAddress((void**)&ybuf,    g_y);
    cudaGetSymbolAddress((void**)&part1,   g_part1);
    cudaGetSymbolAddress((void**)&a1,      g_a1);
    cudaGetSymbolAddress((void**)&bar,     g_bar);

    // 0) transpose recurrent kernels for the GRU
    transpose_rk<<<dim3(30, 10), dim3(32, 32)>>>(fw_rk, rkT);
    transpose_rk<<<dim3(30, 10), dim3(32, 32)>>>(bw_rk, rkT + 960 * 320);

    // 1) Conv1D + bias + relu as GEMM on the stride-4 im2col view (K=104)
    gemm8<256,64,1,1><<<dim3(5, 244, 1), 256>>>(
        inputs, conv_w, conv_b, convout, 62400, 320, 104, 4, 320, 320, 0);

    // 2) MaxPool(13)
    pool_kernel<<<(4800 * 320 + 255) / 256, 256>>>(convout, pooled);

    // 3) GRU input projections (+ input bias): 285 blocks = one full wave each
    gemm8<256,64,0,2><<<dim3(15, 19, 1), 256>>>(
        pooled, fw_k, fw_b, mx,               4800, 960, 320, 320, 960, 960, 0);
    gemm8<256,64,0,2><<<dim3(15, 19, 1), 256>>>(
        pooled, bw_k, bw_b, mx + 4800 * 960,  4800, 960, 320, 320, 960, 960, 0);

    // 4) zero transposed hidden state + grid-barrier counter
    cudaMemsetAsync(hT, 0, 4 * 320 * 64 * sizeof(float));
    cudaMemsetAsync(bar, 0, sizeof(unsigned));

    // 5) all 75 recurrent steps in one persistent kernel
    gru_persistent<<<GRU_BLOCKS, 256>>>(rkT, fw_b, bw_b, mx, hT, ybuf);

    // 6) Dense1 (64,48000)@(48000,2000): 60-way split-K (480 blocks, 2 even waves)
    gemm8<64,256,0,0><<<dim3(8, 1, KSPLIT_D1), 256>>>(
        ybuf, w1, (const float*)0, part1, 64, 2000, 48000, 48000, 2000, 2000, 800);
    reduce_relu<<<(64 * 2000 + 255) / 256, 256>>>(part1, b1, a1);

    // 7) Dense2 + sigmoid
    dense2_kernel<<<dim3(10, 8), dim3(32, 8)>>>(a1, w2, b2, out);

    (void)in_sizes; (void)n_in; (void)out_size;
}

// round 17
// speedup vs baseline: 1.1790x; 1.1414x over previous
#include <cuda_runtime.h>
#include <math.h>
#include <stdint.h>

// ---------------- problem constants ----------------
// B=64, T_IN=1000, C_IN=4, F=320, K=26, POOL=13, T_CONV=975, T_POOL=75
// H=320, 3H=960, FLAT=48000, D1=2000, D2=301
static const int KSPLIT_D1 = 9;    // 48000 -> 8x5344 + 1x5248 (all %32==0)
#define GRU_BLOCKS 160

// ---------------- device scratch (no allocations allowed) ----------------
__device__ float g_convout[62400 * 320];        // (B*975, 320) conv+relu
__device__ float g_pooled [4800 * 320];         // (B*75, 320)
__device__ float g_mx     [2 * 4800 * 960];     // x-projections fw|bw, row = b*75+t
__device__ float g_rkT    [2 * 960 * 320];      // recurrent kernels TRANSPOSED [dir][col][k]
__device__ float g_hT     [4 * 320 * 64];       // [dir][buf] hidden, TRANSPOSED [k][b]
__device__ float g_y      [64 * 48000];         // concat GRU output
__device__ float g_part1  [9 * 64 * 2000];      // dense1 split-K partials
__device__ float g_a1     [64 * 2000];          // dense1 activation
__device__ unsigned g_bar;                      // grid barrier counter (reset each launch)

// ---------------- packed fp32x2 FMA ----------------
__device__ __forceinline__ void ffma2(unsigned long long& d,
                                      unsigned long long a,
                                      unsigned long long b) {
    asm("fma.rn.f32x2 %0, %1, %2, %0;" : "+l"(d) : "l"(a), "l"(b));
}
__device__ __forceinline__ unsigned long long pack2(float x) {
    unsigned long long r;
    asm("mov.b64 %0, {%1, %1};" : "=l"(r) : "f"(x));
    return r;
}
__device__ __forceinline__ void unpack2(unsigned long long v, float& lo, float& hi) {
    asm("mov.b64 {%0, %1}, %2;" : "=f"(lo), "=f"(hi) : "l"(v));
}
// fp32 -> tf32 round-to-nearest (add half-ulp of the 10-bit mantissa before truncation)
__device__ __forceinline__ uint4 rnd4(uint4 v) {
    v.x += 0x1000u; v.y += 0x1000u; v.z += 0x1000u; v.w += 0x1000u;
    return v;
}

// ---------------- dense1 via warp-MMA tf32 (mma.sync, sm_80+ path) ----------------
// D(64x2000) = Y(64x48000) @ W1(48000x2000), fp32 accum, tf32 inputs (RN-rounded).
// grid (16 n-tiles of 128, 9 k-splits) = 144 blocks = one wave; 256 thr = 8 warps.
// Warp tile 16x64 (4 m-warps x 2 n-warps). BK=32, double-buffered dynamic smem.
__global__ __launch_bounds__(256)
void dense1_mma(const float* __restrict__ Y, const float* __restrict__ W1,
                float* __restrict__ part)
{
    extern __shared__ uint32_t dsm[];
    // sA[2][64][36] then sB[2][32][132]
    uint32_t* sAb = dsm;                       // 2*64*36 = 4608 words
    uint32_t* sBb = dsm + 2 * 64 * 36;         // 2*32*132 = 8448 words
#define SA(buf,r,k) sAb[((buf) * 64 + (r)) * 36 + (k)]
#define SB(buf,k,n) sBb[((buf) * 32 + (k)) * 132 + (n)]

    const int tid  = threadIdx.x;
    const int wid  = tid >> 5, lane = tid & 31;
    const int n0   = blockIdx.x * 128;
    const int kz   = blockIdx.y;
    const int kb   = kz * 5344;
    const int ke   = min(48000, kb + 5344);
    const int nt   = (ke - kb) / 32;

    const int wm = (wid >> 1) * 16;            // warp row offset: 0/16/32/48
    const int wn = (wid & 1) * 64;             // warp col offset: 0/64
    const int tg = lane >> 2;                  // 0..7
    const int tl = lane & 3;                   // 0..3

    // A loader: row = tid/4 (0..63), k offset = (tid%4)*8 -> two float4
    const int ar = tid >> 2, akf = (tid & 3) * 8;
    const float* Arow = Y + (size_t)ar * 48000 + kb + akf;
    // B loader: k = tid/8 (0..31), n = (tid%8)*16 -> four float4
    const int bk = tid >> 3, bnf = (tid & 7) * 16;
    bool bv[4];
#pragma unroll
    for (int j = 0; j < 4; j++) bv[j] = (n0 + bnf + j * 4 + 3) < 2000;

    uint4 aR0, aR1, bR[4];
    const uint4 Z4 = make_uint4(0u, 0u, 0u, 0u);
    auto ldg = [&](int t) {
        aR0 = *(const uint4*)(Arow + t * 32);
        aR1 = *(const uint4*)(Arow + t * 32 + 4);
        const float* bp = W1 + (size_t)(kb + t * 32 + bk) * 2000 + n0 + bnf;
#pragma unroll
        for (int j = 0; j < 4; j++) bR[j] = bv[j] ? *(const uint4*)(bp + j * 4) : Z4;
    };
    auto stage = [&](int buf) {
        uint4 v0 = rnd4(aR0), v1 = rnd4(aR1);
        uint32_t* ap = &SA(buf, ar, akf);
        ap[0] = v0.x; ap[1] = v0.y; ap[2] = v0.z; ap[3] = v0.w;
        ap[4] = v1.x; ap[5] = v1.y; ap[6] = v1.z; ap[7] = v1.w;
        uint32_t* bp = &SB(buf, bk, bnf);
#pragma unroll
        for (int j = 0; j < 4; j++) {
            uint4 v = rnd4(bR[j]);
            bp[j * 4 + 0] = v.x; bp[j * 4 + 1] = v.y;
            bp[j * 4 + 2] = v.z; bp[j * 4 + 3] = v.w;
        }
    };

    float acc[8][4];
#pragma unroll
    for (int i = 0; i < 8; i++)
#pragma unroll
        for (int j = 0; j < 4; j++) acc[i][j] = 0.f;

    ldg(0); stage(0); __syncthreads();

    for (int t = 0; t < nt; t++) {
        const int cur = t & 1;
        if (t + 1 < nt) ldg(t + 1);            // next tile's LDG in flight
#pragma unroll
        for (int kk = 0; kk < 4; kk++) {
            // A fragment (m16k8 row-major, PTX-documented lane layout)
            uint32_t a0 = SA(cur, wm + tg,     kk * 8 + tl);
            uint32_t a1 = SA(cur, wm + tg + 8, kk * 8 + tl);
            uint32_t a2 = SA(cur, wm + tg,     kk * 8 + tl + 4);
            uint32_t a3 = SA(cur, wm + tg + 8, kk * 8 + tl + 4);
#pragma unroll
            for (int nti = 0; nti < 8; nti++) {
                uint32_t b0 = SB(cur, kk * 8 + tl,     wn + nti * 8 + tg);
                uint32_t b1 = SB(cur, kk * 8 + tl + 4, wn + nti * 8 + tg);
                asm volatile(
                    "mma.sync.aligned.m16n8k8.row.col.f32.tf32.tf32.f32 "
                    "{%0,%1,%2,%3}, {%4,%5,%6,%7}, {%8,%9}, {%0,%1,%2,%3};"
                    : "+f"(acc[nti][0]), "+f"(acc[nti][1]),
                      "+f"(acc[nti][2]), "+f"(acc[nti][3])
                    : "r"(a0), "r"(a1), "r"(a2), "r"(a3), "r"(b0), "r"(b1));
            }
        }
        if (t + 1 < nt) stage(cur ^ 1);
        __syncthreads();
    }

    // epilogue: D lane layout c0/c1 -> (row, 2*tl), c2/c3 -> (row+8, 2*tl)
    float* pr = part + (size_t)kz * 128000;
    const int row0 = wm + tg;
#pragma unroll
    for (int nti = 0; nti < 8; nti++) {
        const int col = n0 + wn + nti * 8 + 2 * tl;
        if (col < 2000) {                       // col even, 2000 even -> col+1 ok too
            pr[(size_t)row0 * 2000 + col]           = acc[nti][0];
            pr[(size_t)row0 * 2000 + col + 1]       = acc[nti][1];
            pr[(size_t)(row0 + 8) * 2000 + col]     = acc[nti][2];
            pr[(size_t)(row0 + 8) * 2000 + col + 1] = acc[nti][3];
        }
    }
#undef SA
#undef SB
}

// ---------------- fp32 GEMM, 8x8/thread via FFMA2, BK=8, double-buffered ----------------
template<int BM,int BN,int AMODE,int EPI>
__global__ __launch_bounds__(256, 2)
void gemm8(const float* __restrict__ A, const float* __restrict__ Bm,
           const float* __restrict__ bias, float* __restrict__ C,
           int M, int N, int K, int lda, int ldb, int ldc, int kchunk)
{
    constexpr int TX = BN / 8, TY = BM / 8;
    static_assert(TX * TY == 256, "need 256 threads");
    __shared__ float sA[2][8][BM + 4];
    __shared__ __align__(16) float sB[2][8][BN];

    const int tid = threadIdx.x;
    const int tx = tid % TX, ty = tid / TX;
    const int m0 = blockIdx.y * BM;
    const int n0 = blockIdx.x * BN;

    int kb = 0, ke = K;
    float* Cout = C;
    if (kchunk > 0) {
        kb = blockIdx.z * kchunk;
        ke = kb + kchunk;
        Cout = C + (size_t)blockIdx.z * (size_t)M * (size_t)ldc;
    }

    int alr, alk;
    if constexpr (BM == 256)      { alr = tid;      alk = 0; }
    else if constexpr (BM == 128) { alr = tid >> 1; alk = (tid & 1) * 4; }
    else                          { alr = tid >> 2; alk = (tid & 3) * 2; }
    const int arow = m0 + alr;
    const bool aval = arow < M;
    size_t abase;
    if (AMODE == 1) abase = aval ? (size_t)(arow / 975) * 4000 + (size_t)(arow % 975) * 4 : 0;
    else            abase = aval ? (size_t)arow * (size_t)lda : 0;

    const int blk = tid >> 5;
    const int blc = (BN == 64) ? (tid & 31) * 2 : (tid & 31) * 4;
    const bool fullN = (n0 + BN <= N);

    float4 apre  = make_float4(0.f, 0.f, 0.f, 0.f);
    float4 apre2 = make_float4(0.f, 0.f, 0.f, 0.f);
    float4 bpre0 = make_float4(0.f, 0.f, 0.f, 0.f);
    float4 bpre1 = make_float4(0.f, 0.f, 0.f, 0.f);

    auto loadAB = [&](int k0) {
        if constexpr (BM == 256) {
            if (aval) {
                apre  = *(const float4*)(A + abase + k0);
                apre2 = *(const float4*)(A + abase + k0 + 4);
            }
        } else if constexpr (BM == 128) {
            if (aval) apre = *(const float4*)(A + abase + k0 + alk);
        } else {
            if (aval) { float2 v = *(const float2*)(A + abase + k0 + alk); apre.x = v.x; apre.y = v.y; }
        }
        const float* bp = Bm + (size_t)(k0 + blk) * (size_t)ldb + n0 + blc;
        if constexpr (BN == 64) {
            if (fullN) { float2 v = *(const float2*)bp; bpre0.x = v.x; bpre0.y = v.y; }
            else {
                bpre0.x = (n0 + blc     < N) ? bp[0] : 0.f;
                bpre0.y = (n0 + blc + 1 < N) ? bp[1] : 0.f;
            }
        } else {
            if (fullN) {
                bpre0 = *(const float4*)bp;
                if constexpr (BN == 256) bpre1 = *(const float4*)(bp + 128);
            } else {
                float t0[4];
#pragma unroll
                for (int j = 0; j < 4; j++) t0[j] = (n0 + blc + j < N) ? bp[j] : 0.f;
                bpre0 = make_float4(t0[0], t0[1], t0[2], t0[3]);
                if constexpr (BN == 256) {
                    float t1[4];
#pragma unroll
                    for (int j = 0; j < 4; j++) t1[j] = (n0 + blc + 128 + j < N) ? bp[128 + j] : 0.f;
                    bpre1 = make_float4(t1[0], t1[1], t1[2], t1[3]);
                }
            }
        }
    };
    auto stage = [&](int buf) {
        if constexpr (BM == 256) {
            sA[buf][0][alr] = apre.x;  sA[buf][1][alr] = apre.y;
            sA[buf][2][alr] = apre.z;  sA[buf][3][alr] = apre.w;
            sA[buf][4][alr] = apre2.x; sA[buf][5][alr] = apre2.y;
            sA[buf][6][alr] = apre2.z; sA[buf][7][alr] = apre2.w;
        } else if constexpr (BM == 128) {
            sA[buf][alk + 0][alr] = apre.x; sA[buf][alk + 1][alr] = apre.y;
            sA[buf][alk + 2][alr] = apre.z; sA[buf][alk + 3][alr] = apre.w;
        } else {
            sA[buf][alk + 0][alr] = apre.x; sA[buf][alk + 1][alr] = apre.y;
        }
        if constexpr (BN == 64) {
            sB[buf][blk][blc] = bpre0.x; sB[buf][blk][blc + 1] = bpre0.y;
        } else {
            *(float4*)&sB[buf][blk][blc] = bpre0;
            if constexpr (BN == 256) *(float4*)&sB[buf][blk][blc + 128] = bpre1;
        }
    };

    unsigned long long acc2[8][4];
#pragma unroll
    for (int i = 0; i < 8; i++)
#pragma unroll
        for (int j = 0; j < 4; j++) acc2[i][j] = 0ull;

    const int nt = (ke - kb) / 8;
    loadAB(kb);
    stage(0);
    __syncthreads();

    for (int t = 0; t < nt; t++) {
        const int cur = t & 1;
        if (t + 1 < nt) loadAB(kb + (t + 1) * 8);
#pragma unroll
        for (int kk = 0; kk < 8; kk++) {
            float4 a0 = *(const float4*)&sA[cur][kk][ty * 8];
            float4 a1 = *(const float4*)&sA[cur][kk][ty * 8 + 4];
            const unsigned long long* bp =
                (const unsigned long long*)&sB[cur][kk][tx * 8];
            unsigned long long b2[4] = {bp[0], bp[1], bp[2], bp[3]};
            float ra[8] = {a0.x, a0.y, a0.z, a0.w, a1.x, a1.y, a1.z, a1.w};
#pragma unroll
            for (int i = 0; i < 8; i++) {
                unsigned long long ap = pack2(ra[i]);
                ffma2(acc2[i][0], ap, b2[0]);
                ffma2(acc2[i][1], ap, b2[1]);
                ffma2(acc2[i][2], ap, b2[2]);
                ffma2(acc2[i][3], ap, b2[3]);
            }
        }
        if (t + 1 < nt) stage(cur ^ 1);
        __syncthreads();
    }

#pragma unroll
    for (int i = 0; i < 8; i++) {
        int row = m0 + ty * 8 + i;
        if (row >= M) continue;
        float* crow = Cout + (size_t)row * (size_t)ldc;
#pragma unroll
        for (int j = 0; j < 4; j++) {
            float lo, hi;
            unpack2(acc2[i][j], lo, hi);
#pragma unroll
            for (int e = 0; e < 2; e++) {
                int col = n0 + tx * 8 + 2 * j + e;
                if (col >= N) continue;
                float v = e ? hi : lo;
                if (kchunk == 0) {
                    if (EPI == 1)      v = fmaxf(v + bias[col], 0.f);
                    else if (EPI == 2) v = v + bias[col];
                }
                crow[col] = v;
            }
        }
    }
}

// ---------------- maxpool over 13 conv rows ----------------
__global__ __launch_bounds__(256)
void pool_kernel(const float* __restrict__ conv, float* __restrict__ pooled)
{
    int idx = blockIdx.x * 256 + threadIdx.x;
    if (idx >= 4800 * 320) return;
    int f = idx % 320;
    int bp = idx / 320;
    int b = bp / 75, p = bp % 75;
    const float* src = conv + ((size_t)(b * 975 + p * 13)) * 320 + f;
    float m = src[0];
#pragma unroll
    for (int q = 1; q < 13; q++) m = fmaxf(m, src[(size_t)q * 320]);
    pooled[idx] = m;
}

// ---------------- transpose rk (320,960) -> rkT (960,320) ----------------
__global__ void transpose_rk(const float* __restrict__ rk, float* __restrict__ rkT)
{
    __shared__ float tile[32][33];
    int c0 = blockIdx.x * 32, k0 = blockIdx.y * 32;
    tile[threadIdx.y][threadIdx.x] = rk[(size_t)(k0 + threadIdx.y) * 960 + c0 + threadIdx.x];
    __syncthreads();
    rkT[(size_t)(c0 + threadIdx.y) * 320 + k0 + threadIdx.x] = tile[threadIdx.x][threadIdx.y];
}

// ---------------- persistent GRU: all 75 steps in ONE kernel ----------------
__global__ __launch_bounds__(256, 2)
void gru_persistent(const float* __restrict__ rkT_all,
                    const float* __restrict__ b_fw,  const float* __restrict__ b_bw,
                    const float* __restrict__ mx_all,
                    float* __restrict__ hT, float* __restrict__ y)
{
    const int bid = blockIdx.x;
    const int dir = bid & 1;
    const int u0  = (bid >> 1) * 4;
    const int tid = threadIdx.x;
    const int bq  = tid & 31;       // batch pair: b = bq*2, bq*2+1
    const int ks  = tid >> 5;       // 0..7, covers k in [ks*40, ks*40+40)

    const float* rkT = rkT_all + (size_t)dir * (960 * 320);
    const float* br  = (dir ? b_bw : b_fw) + 960;
    const float* mxd = mx_all + (size_t)dir * (4800 * 960);
    float* hbase = hT + (size_t)(dir * 2) * 20480;

    __shared__ float srk[12][320];
    __shared__ float sred[8 * 64 * 13];

    for (int i = tid; i < 12 * 320; i += 256) {
        int c = i / 320, k = i - c * 320;
        int gcol = (c >> 2) * 320 + u0 + (c & 3);
        srk[c][k] = rkT[(size_t)gcol * 320 + k];
    }
    __syncthreads();

    for (int s = 0; s < 75; s++) {
        const int cur = s & 1;
        const int t   = dir ? (74 - s) : s;
        const float* hcur = hbase + cur * 20480;

        float acc[2][12];
#pragma unroll
        for (int c = 0; c < 12; c++) { acc[0][c] = 0.f; acc[1][c] = 0.f; }

        const int kb = ks * 40;
#pragma unroll 2
        for (int kc = 0; kc < 40; kc += 4) {
            const int k0 = kb + kc;
            float2 hv0 = __ldcg((const float2*)(hcur + (size_t)(k0 + 0) * 64 + bq * 2));
            float2 hv1 = __ldcg((const float2*)(hcur + (size_t)(k0 + 1) * 64 + bq * 2));
            float2 hv2 = __ldcg((const float2*)(hcur + (size_t)(k0 + 2) * 64 + bq * 2));
            float2 hv3 = __ldcg((const float2*)(hcur + (size_t)(k0 + 3) * 64 + bq * 2));
#pragma unroll
            for (int c = 0; c < 12; c++) {
                float4 r = *(const float4*)&srk[c][k0];
                acc[0][c] = fmaf(hv0.x, r.x, acc[0][c]);
                acc[1][c] = fmaf(hv0.y, r.x, acc[1][c]);
                acc[0][c] = fmaf(hv1.x, r.y, acc[0][c]);
                acc[1][c] = fmaf(hv1.y, r.y, acc[1][c]);
                acc[0][c] = fmaf(hv2.x, r.z, acc[0][c]);
                acc[1][c] = fmaf(hv2.y, r.z, acc[1][c]);
                acc[0][c] = fmaf(hv3.x, r.w, acc[0][c]);
                acc[1][c] = fmaf(hv3.y, r.w, acc[1][c]);
            }
        }

#pragma unroll
        for (int i = 0; i < 2; i++) {
            float* p = &sred[((size_t)ks * 64 + bq * 2 + i) * 13];
#pragma unroll
            for (int c = 0; c < 12; c++) p[c] = acc[i][c];
        }
        __syncthreads();

        {
            const int b  = tid >> 2;
            const int uu = tid & 3;
            const int c  = u0 + uu;
            float sz = 0.f, sr = 0.f, sh = 0.f;
#pragma unroll
            for (int z = 0; z < 8; z++) {
                const float* p = &sred[((size_t)z * 64 + b) * 13];
                sz += p[uu]; sr += p[4 + uu]; sh += p[8 + uu];
            }
            const float* mx = mxd + (size_t)(b * 75 + t) * 960;
            float hold = __ldcg(hcur + (size_t)c * 64 + b);
            float zg   = 1.f / (1.f + expf(-(mx[c]       + sz + br[c])));
            float rg   = 1.f / (1.f + expf(-(mx[320 + c] + sr + br[320 + c])));
            float cand = tanhf(mx[640 + c] + rg * (sh + br[640 + c]));
            float hn   = zg * hold + (1.f - zg) * cand;
            hbase[(size_t)(cur ^ 1) * 20480 + (size_t)c * 64 + b] = hn;
            y[(size_t)b * 48000 + (size_t)t * 640 + dir * 320 + c] = hn;
        }

        if (s < 74) {
            __threadfence();
            __syncthreads();
            if (tid == 0) {
                atomicAdd(&g_bar, 1u);
                const unsigned target = (unsigned)GRU_BLOCKS * (unsigned)(s + 1);
                volatile unsigned* p = &g_bar;
                while (*p < target) __nanosleep(64);
            }
            __syncthreads();
        }
    }
}

// ---------------- dense1 split-K reduce + bias + relu ----------------
__global__ __launch_bounds__(256)
void reduce_relu(const float* __restrict__ part, const float* __restrict__ bias,
                 float* __restrict__ out)
{
    int i = blockIdx.x * 256 + threadIdx.x;
    if (i >= 64 * 2000) return;
    float s = bias[i % 2000];
#pragma unroll
    for (int z = 0; z < KSPLIT_D1; z++) s += part[(size_t)z * 128000 + i];
    out[i] = fmaxf(s, 0.f);
}

// ---------------- dense2 + sigmoid ----------------
__global__ void dense2_kernel(const float* __restrict__ a1, const float* __restrict__ w2,
                              const float* __restrict__ b2, float* __restrict__ out)
{
    int n = blockIdx.x * 32 + threadIdx.x;
    int b = blockIdx.y * 8 + threadIdx.y;
    if (n >= 301) return;
    float acc = b2[n];
    const float* arow = a1 + (size_t)b * 2000;
#pragma unroll 4
    for (int k = 0; k < 2000; k++)
        acc = fmaf(arow[k], w2[(size_t)k * 301 + n], acc);
    out[(size_t)b * 301 + n] = 1.f / (1.f + expf(-acc));
}

// ---------------- launcher ----------------
extern "C" void kernel_launch(void* const* d_in, const int* in_sizes, int n_in,
                              void* d_out, int out_size)
{
    const float* inputs = (const float*)d_in[0];
    const float* conv_w = (const float*)d_in[1];
    const float* conv_b = (const float*)d_in[2];
    const float* fw_k   = (const float*)d_in[3];
    const float* fw_rk  = (const float*)d_in[4];
    const float* fw_b   = (const float*)d_in[5];
    const float* bw_k   = (const float*)d_in[6];
    const float* bw_rk  = (const float*)d_in[7];
    const float* bw_b   = (const float*)d_in[8];
    const float* w1     = (const float*)d_in[9];
    const float* b1     = (const float*)d_in[10];
    const float* w2     = (const float*)d_in[11];
    const float* b2     = (const float*)d_in[12];
    float* out = (float*)d_out;

    float *convout, *pooled, *mx, *rkT, *hT, *ybuf, *part1, *a1;
    unsigned* bar;
    cudaGetSymbolAddress((void**)&convout, g_convout);
    cudaGetSymbolAddress((void**)&pooled,  g_pooled);
    cudaGetSymbolAddress((void**)&mx,      g_mx);
    cudaGetSymbolAddress((void**)&rkT,     g_rkT);
    cudaGetSymbolAddress((void**)&hT,      g_hT);
    cudaGetSymbolAddress((void**)&ybuf,    g_y);
    cudaGetSymbolAddress((void**)&part1,   g_part1);
    cudaGetSymbolAddress((void**)&a1,      g_a1);
    cudaGetSymbolAddress((void**)&bar,     g_bar);

    // 0) transpose recurrent kernels for the GRU
    transpose_rk<<<dim3(30, 10), dim3(32, 32)>>>(fw_rk, rkT);
    transpose_rk<<<dim3(30, 10), dim3(32, 32)>>>(bw_rk, rkT + 960 * 320);

    // 1) Conv1D + bias + relu as GEMM on the stride-4 im2col view (K=104)
    gemm8<256,64,1,1><<<dim3(5, 244, 1), 256>>>(
        inputs, conv_w, conv_b, convout, 62400, 320, 104, 4, 320, 320, 0);

    // 2) MaxPool(13)
    pool_kernel<<<(4800 * 320 + 255) / 256, 256>>>(convout, pooled);

    // 3) GRU input projections (+ input bias)
    gemm8<256,64,0,2><<<dim3(15, 19, 1), 256>>>(
        pooled, fw_k, fw_b, mx,               4800, 960, 320, 320, 960, 960, 0);
    gemm8<256,64,0,2><<<dim3(15, 19, 1), 256>>>(
        pooled, bw_k, bw_b, mx + 4800 * 960,  4800, 960, 320, 320, 960, 960, 0);

    // 4) zero transposed hidden state + grid-barrier counter
    cudaMemsetAsync(hT, 0, 4 * 320 * 64 * sizeof(float));
    cudaMemsetAsync(bar, 0, sizeof(unsigned));

    // 5) all 75 recurrent steps in one persistent kernel
    gru_persistent<<<GRU_BLOCKS, 256>>>(rkT, fw_b, bw_b, mx, hT, ybuf);

    // 6) Dense1 via warp-MMA tf32: (16 n-tiles, 9 k-splits) = 144 blocks, one wave
    {
        const int SMEM_D1 = (2 * 64 * 36 + 2 * 32 * 132) * 4;   // 52224 bytes
        cudaFuncSetAttribute(dense1_mma, cudaFuncAttributeMaxDynamicSharedMemorySize, SMEM_D1);
        dense1_mma<<<dim3(16, 9), 256, SMEM_D1>>>(ybuf, w1, part1);
    }
    reduce_relu<<<(64 * 2000 + 255) / 256, 256>>>(part1, b1, a1);

    // 7) Dense2 + sigmoid
    dense2_kernel<<<dim3(10, 8), dim3(32, 8)>>>(a1, w2, b2, out);

    (void)in_sizes; (void)n_in; (void)out_size;
}